// round 4
// baseline (speedup 1.0000x reference)
#include <cuda_runtime.h>
#include <cuda_bf16.h>
#include <cuda_fp16.h>
#include <cstdint>

// ---------------- problem constants ----------------
#define N_NODES 4096
#define F_IN    512
#define N_HEADS 4
#define N_HID   256
#define HD      1024     // N_HEADS*N_HID
#define NP2     1152     // 1024 feature cols + 4 Z cols, padded to 9*128

// ---------------- scratch (device globals; allocation-free) ----------------
__device__ uint16_t g_hh [N_NODES * F_IN];            // bf16 hi of h
__device__ uint16_t g_hl [N_NODES * F_IN];            // bf16 lo of h
__device__ uint16_t g_Wh [F_IN * HD];                 // bf16 hi of W
__device__ uint16_t g_Wl [F_IN * HD];                 // bf16 lo of W
__device__ uint16_t g_adjh[(size_t)N_NODES * N_NODES];// fp16 adjacency {0,1}
__device__ uint16_t g_V  [(size_t)N_NODES * NP2];     // fp16 weighted V
__device__ float    g_HT [N_NODES * HD];              // h@W fp32
__device__ float    g_Y  [(size_t)N_NODES * NP2];     // adj@V fp32
__device__ float    g_tgt [N_HEADS * N_NODES];
__device__ float    g_tmax[N_HEADS];

// ---------------- small helpers ----------------
__device__ __forceinline__ uint32_t smem_u32(const void* p) {
    uint32_t a;
    asm("{ .reg .u64 t; cvta.to.shared.u64 t, %1; cvt.u32.u64 %0, t; }" : "=r"(a) : "l"(p));
    return a;
}
__device__ __forceinline__ uint32_t pk(uint16_t a, uint16_t b) {
    return (uint32_t)a | ((uint32_t)b << 16);
}

__device__ __forceinline__ void cpasync16(uint32_t dst, const void* src) {
    asm volatile("cp.async.cg.shared.global [%0], [%1], 16;" :: "r"(dst), "l"(src));
}
__device__ __forceinline__ void cp_commit() {
    asm volatile("cp.async.commit_group;" ::: "memory");
}
template <int N>
__device__ __forceinline__ void cp_wait() {
    asm volatile("cp.async.wait_group %0;" :: "n"(N) : "memory");
}

__device__ __forceinline__ void ldsm4(uint32_t& r0, uint32_t& r1, uint32_t& r2, uint32_t& r3,
                                      uint32_t addr) {
    asm volatile("ldmatrix.sync.aligned.m8n8.x4.shared.b16 {%0,%1,%2,%3}, [%4];"
                 : "=r"(r0), "=r"(r1), "=r"(r2), "=r"(r3) : "r"(addr));
}
__device__ __forceinline__ void ldsm4t(uint32_t& r0, uint32_t& r1, uint32_t& r2, uint32_t& r3,
                                       uint32_t addr) {
    asm volatile("ldmatrix.sync.aligned.m8n8.x4.trans.shared.b16 {%0,%1,%2,%3}, [%4];"
                 : "=r"(r0), "=r"(r1), "=r"(r2), "=r"(r3) : "r"(addr));
}

template <bool BF>
__device__ __forceinline__ void mma16816(float* c, const uint32_t* a, const uint32_t* b) {
    if (BF)
        asm volatile(
            "mma.sync.aligned.m16n8k16.row.col.f32.bf16.bf16.f32 "
            "{%0,%1,%2,%3},{%4,%5,%6,%7},{%8,%9},{%0,%1,%2,%3};"
            : "+f"(c[0]), "+f"(c[1]), "+f"(c[2]), "+f"(c[3])
            : "r"(a[0]), "r"(a[1]), "r"(a[2]), "r"(a[3]), "r"(b[0]), "r"(b[1]));
    else
        asm volatile(
            "mma.sync.aligned.m16n8k16.row.col.f32.f16.f16.f32 "
            "{%0,%1,%2,%3},{%4,%5,%6,%7},{%8,%9},{%0,%1,%2,%3};"
            : "+f"(c[0]), "+f"(c[1]), "+f"(c[2]), "+f"(c[3])
            : "r"(a[0]), "r"(a[1]), "r"(a[2]), "r"(a[3]), "r"(b[0]), "r"(b[1]));
}

// ---------------- prep kernels ----------------
__global__ void split_kernel(const float4* __restrict__ src,
                             uint4* __restrict__ hh, uint4* __restrict__ hl) {
    int i = blockIdx.x * 256 + threadIdx.x;
    float4 v0 = src[2 * i], v1 = src[2 * i + 1];
    float f[8] = {v0.x, v0.y, v0.z, v0.w, v1.x, v1.y, v1.z, v1.w};
    uint16_t H[8], L[8];
    #pragma unroll
    for (int j = 0; j < 8; j++) {
        __nv_bfloat16 b = __float2bfloat16(f[j]);
        H[j] = __bfloat16_as_ushort(b);
        L[j] = __bfloat16_as_ushort(__float2bfloat16(f[j] - __bfloat162float(b)));
    }
    hh[i] = make_uint4(pk(H[0], H[1]), pk(H[2], H[3]), pk(H[4], H[5]), pk(H[6], H[7]));
    hl[i] = make_uint4(pk(L[0], L[1]), pk(L[2], L[3]), pk(L[4], L[5]), pk(L[6], L[7]));
}

__global__ void prep_adj(const int4* __restrict__ adj, uint4* __restrict__ out) {
    int i = blockIdx.x * 256 + threadIdx.x;
    int4 a0 = adj[2 * i], a1 = adj[2 * i + 1];
    int v[8] = {a0.x, a0.y, a0.z, a0.w, a1.x, a1.y, a1.z, a1.w};
    uint16_t hv[8];
    #pragma unroll
    for (int j = 0; j < 8; j++) hv[j] = (v[j] > 0) ? (uint16_t)0x3C00 : (uint16_t)0;
    out[i] = make_uint4(pk(hv[0], hv[1]), pk(hv[2], hv[3]), pk(hv[4], hv[5]), pk(hv[6], hv[7]));
}

__global__ void tgt_kernel(const float* __restrict__ HT, const float* __restrict__ a,
                           float* __restrict__ tgt) {
    int warp = (blockIdx.x * blockDim.x + threadIdx.x) >> 5;
    int lane = threadIdx.x & 31;
    if (warp >= N_HEADS * N_NODES) return;
    int h = warp >> 12, m = warp & 4095;
    const float* row = HT + (size_t)m * HD + h * N_HID;
    const float* av  = a + h * (2 * N_HID) + N_HID;
    float s = 0.0f;
    #pragma unroll
    for (int d = lane; d < N_HID; d += 32) {
        float x = row[d];
        x = (x > 0.0f) ? x : 0.1f * x;
        s += x * av[d];
    }
    #pragma unroll
    for (int o = 16; o; o >>= 1) s += __shfl_xor_sync(0xFFFFFFFFu, s, o);
    if (lane == 0) tgt[h * N_NODES + m] = s;
}

__global__ void tmax_kernel(const float* __restrict__ tgt, float* __restrict__ tmax) {
    int h = blockIdx.x;
    __shared__ float sm[256];
    float m = -1e30f;
    for (int i = threadIdx.x; i < N_NODES; i += 256)
        m = fmaxf(m, tgt[h * N_NODES + i]);
    sm[threadIdx.x] = m;
    __syncthreads();
    for (int s = 128; s; s >>= 1) {
        if (threadIdx.x < s) sm[threadIdx.x] = fmaxf(sm[threadIdx.x], sm[threadIdx.x + s]);
        __syncthreads();
    }
    if (threadIdx.x == 0) tmax[h] = sm[0];
}

// w' = exp(tgt - tmax) * 4096 (scale cancels in ratio; keeps fp16 normal)
__global__ void buildV(const float* __restrict__ HT, const float* __restrict__ tgt,
                       const float* __restrict__ tmax, __half* __restrict__ V) {
    int n = blockIdx.x;
    __shared__ float w[N_HEADS];
    if (threadIdx.x < N_HEADS)
        w[threadIdx.x] = expf(tgt[threadIdx.x * N_NODES + n] - tmax[threadIdx.x]) * 4096.0f;
    __syncthreads();
    __half* row = V + (size_t)n * NP2;
    const float* ht = HT + (size_t)n * HD;
    for (int c = threadIdx.x; c < NP2; c += 256) {
        float v;
        if (c < HD)          v = w[c >> 8] * ht[c];
        else if (c < HD + 4) v = w[c - HD];
        else                 v = 0.0f;
        row[c] = __float2half(v);
    }
}

__global__ void final_kernel(const float* __restrict__ Y, float* __restrict__ out) {
    int i = blockIdx.x * 256 + threadIdx.x;
    int n = i >> 8, d = i & 255;
    const float* yr = Y + (size_t)n * NP2;
    float acc = 0.0f;
    #pragma unroll
    for (int h = 0; h < N_HEADS; h++)
        acc += yr[h * N_HID + d] / yr[HD + h];
    out[i] = 0.25f * acc;
}

// ---------------- shared GEMM geometry ----------------
#define BM 128
#define BN 128
#define BK 32
#define A_STRIDE 80      // bytes: 64B data + 16B pad per A row (conflict-free ldsm)
#define B_STRIDE 272     // bytes: 256B data + 16B pad per B row
#define A_TILE   (BM * A_STRIDE)   // 10240 B
#define B_TILE   (BK * B_STRIDE)   // 8704 B

// ---------------- GEMM1 kernel: 8 warps, warp tile 64x32, multi-product ----------------
template <int NA, int NB, int STAGES, bool BF>
__global__ void __launch_bounds__(256)
gemm_mma(const uint16_t* __restrict__ A1, const uint16_t* __restrict__ A2,
         const uint16_t* __restrict__ B1, const uint16_t* __restrict__ B2,
         float* __restrict__ C, int N, int K) {
    extern __shared__ __align__(128) char smem[];
    const uint32_t sb = smem_u32(smem);
    const int tid = threadIdx.x, lane = tid & 31, wid = tid >> 5;
    const int wm = wid >> 2, wn = wid & 3;
    const int bm = blockIdx.y * BM, bn = blockIdx.x * BN;
    constexpr uint32_t STAGE = NA * A_TILE + NB * B_TILE;

    const uint16_t* Ap[2] = {A1, A2};
    const uint16_t* Bp[2] = {B1, B2};

    const int arow = tid >> 2, ac16 = tid & 3;
    const int brow = tid >> 4, bc16 = tid & 15;

    auto load_stage = [&](int slot, int k0) {
        uint32_t base = sb + slot * STAGE;
        #pragma unroll
        for (int p = 0; p < NA; p++) {
            uint32_t ab = base + p * A_TILE;
            const uint16_t* g = Ap[p] + (size_t)(bm + arow) * K + k0 + ac16 * 8;
            cpasync16(ab + arow * A_STRIDE + ac16 * 16, g);
            cpasync16(ab + (arow + 64) * A_STRIDE + ac16 * 16, g + (size_t)64 * K);
        }
        #pragma unroll
        for (int p = 0; p < NB; p++) {
            uint32_t bb = base + NA * A_TILE + p * B_TILE;
            const uint16_t* g = Bp[p] + (size_t)(k0 + brow) * N + bn + bc16 * 8;
            cpasync16(bb + brow * B_STRIDE + bc16 * 16, g);
            cpasync16(bb + (brow + 16) * B_STRIDE + bc16 * 16, g + (size_t)16 * N);
        }
        cp_commit();
    };

    const int iters = K / BK;
    #pragma unroll
    for (int s = 0; s < STAGES - 1; s++)
        load_stage(s, s * BK);

    float acc[4][4][4];
    #pragma unroll
    for (int i = 0; i < 4; i++)
        #pragma unroll
        for (int j = 0; j < 4; j++)
            #pragma unroll
            for (int r = 0; r < 4; r++) acc[i][j][r] = 0.0f;

    const int lrow = lane & 15;
    const int lcol = lane >> 4;

    for (int it = 0; it < iters; ++it) {
        cp_wait<STAGES - 2>();
        __syncthreads();
        if (it + STAGES - 1 < iters)
            load_stage((it + STAGES - 1) % STAGES, (it + STAGES - 1) * BK);

        uint32_t base = sb + (it % STAGES) * STAGE;
        #pragma unroll
        for (int ks = 0; ks < 2; ks++) {
            uint32_t af[2][4][4];
            uint32_t bf[2][2][4];
            #pragma unroll
            for (int p = 0; p < NA; p++)
                #pragma unroll
                for (int mt = 0; mt < 4; mt++) {
                    uint32_t addr = base + p * A_TILE
                                  + (wm * 64 + mt * 16 + lrow) * A_STRIDE
                                  + ks * 32 + lcol * 16;
                    ldsm4(af[p][mt][0], af[p][mt][1], af[p][mt][2], af[p][mt][3], addr);
                }
            #pragma unroll
            for (int p = 0; p < NB; p++)
                #pragma unroll
                for (int nt2 = 0; nt2 < 2; nt2++) {
                    uint32_t addr = base + NA * A_TILE + p * B_TILE
                                  + (ks * 16 + lrow) * B_STRIDE
                                  + (wn * 32 + nt2 * 16 + lcol * 8) * 2;
                    ldsm4t(bf[p][nt2][0], bf[p][nt2][1], bf[p][nt2][2], bf[p][nt2][3], addr);
                }
            #pragma unroll
            for (int mt = 0; mt < 4; mt++)
                #pragma unroll
                for (int nt = 0; nt < 4; nt++) {
                    const uint32_t* b0 = &bf[0][nt >> 1][(nt & 1) * 2];
                    mma16816<BF>(acc[mt][nt], af[0][mt], b0);
                    if (NB == 2) mma16816<BF>(acc[mt][nt], af[0][mt], &bf[1][nt >> 1][(nt & 1) * 2]);
                    if (NA == 2) mma16816<BF>(acc[mt][nt], af[1][mt], b0);
                }
        }
    }

    const int row0 = bm + wm * 64;
    const int col0 = bn + wn * 32;
    #pragma unroll
    for (int mt = 0; mt < 4; mt++)
        #pragma unroll
        for (int nt = 0; nt < 4; nt++) {
            int r = row0 + mt * 16 + (lane >> 2);
            int c = col0 + nt * 8 + (lane & 3) * 2;
            *(float2*)&C[(size_t)r * N + c]       = make_float2(acc[mt][nt][0], acc[mt][nt][1]);
            *(float2*)&C[(size_t)(r + 8) * N + c] = make_float2(acc[mt][nt][2], acc[mt][nt][3]);
        }
}

// ---------------- GEMM2 kernel: 4 warps, warp tile 64x64, fp16, single product ----------
template <int STAGES>
__global__ void __launch_bounds__(128)
gemm_mma64(const uint16_t* __restrict__ A, const uint16_t* __restrict__ B,
           float* __restrict__ C, int N, int K) {
    extern __shared__ __align__(128) char smem[];
    const uint32_t sb = smem_u32(smem);
    const int tid = threadIdx.x, lane = tid & 31, wid = tid >> 5;
    const int wm = wid >> 1, wn = wid & 1;
    const int bm = blockIdx.y * BM, bn = blockIdx.x * BN;
    constexpr uint32_t STAGE = A_TILE + B_TILE;

    auto load_stage = [&](int slot, int k0) {
        uint32_t base = sb + slot * STAGE;
        #pragma unroll
        for (int i = 0; i < 4; i++) {
            int idx = i * 128 + tid;            // A: 512 chunks of 16B
            int row = idx >> 2, c16 = idx & 3;
            cpasync16(base + row * A_STRIDE + c16 * 16,
                      A + (size_t)(bm + row) * K + k0 + c16 * 8);
        }
        #pragma unroll
        for (int i = 0; i < 4; i++) {
            int idx = i * 128 + tid;            // B: 512 chunks of 16B
            int row = idx >> 4, c16 = idx & 15;
            cpasync16(base + A_TILE + row * B_STRIDE + c16 * 16,
                      B + (size_t)(k0 + row) * N + bn + c16 * 8);
        }
        cp_commit();
    };

    const int iters = K / BK;
    #pragma unroll
    for (int s = 0; s < STAGES - 1; s++)
        load_stage(s, s * BK);

    float acc[4][8][4];
    #pragma unroll
    for (int i = 0; i < 4; i++)
        #pragma unroll
        for (int j = 0; j < 8; j++)
            #pragma unroll
            for (int r = 0; r < 4; r++) acc[i][j][r] = 0.0f;

    const int lrow = lane & 15;
    const int lcol = lane >> 4;

    for (int it = 0; it < iters; ++it) {
        cp_wait<STAGES - 2>();
        __syncthreads();
        if (it + STAGES - 1 < iters)
            load_stage((it + STAGES - 1) % STAGES, (it + STAGES - 1) * BK);

        uint32_t base = sb + (it % STAGES) * STAGE;
        #pragma unroll
        for (int ks = 0; ks < 2; ks++) {
            uint32_t af[4][4];
            uint32_t bf[4][4];
            #pragma unroll
            for (int mt = 0; mt < 4; mt++) {
                uint32_t addr = base + (wm * 64 + mt * 16 + lrow) * A_STRIDE
                              + ks * 32 + lcol * 16;
                ldsm4(af[mt][0], af[mt][1], af[mt][2], af[mt][3], addr);
            }
            #pragma unroll
            for (int nt2 = 0; nt2 < 4; nt2++) {
                uint32_t addr = base + A_TILE + (ks * 16 + lrow) * B_STRIDE
                              + (wn * 64 + nt2 * 16 + lcol * 8) * 2;
                ldsm4t(bf[nt2][0], bf[nt2][1], bf[nt2][2], bf[nt2][3], addr);
            }
            #pragma unroll
            for (int mt = 0; mt < 4; mt++)
                #pragma unroll
                for (int nt = 0; nt < 8; nt++)
                    mma16816<false>(acc[mt][nt], af[mt], &bf[nt >> 1][(nt & 1) * 2]);
        }
    }

    const int row0 = bm + wm * 64;
    const int col0 = bn + wn * 64;
    #pragma unroll
    for (int mt = 0; mt < 4; mt++)
        #pragma unroll
        for (int nt = 0; nt < 8; nt++) {
            int r = row0 + mt * 16 + (lane >> 2);
            int c = col0 + nt * 8 + (lane & 3) * 2;
            *(float2*)&C[(size_t)r * N + c]       = make_float2(acc[mt][nt][0], acc[mt][nt][1]);
            *(float2*)&C[(size_t)(r + 8) * N + c] = make_float2(acc[mt][nt][2], acc[mt][nt][3]);
        }
}

// ---------------- launch ----------------
extern "C" void kernel_launch(void* const* d_in, const int* in_sizes, int n_in,
                              void* d_out, int out_size) {
    const float* h = nullptr; const int* adj = nullptr;
    const float* W = nullptr; const float* a = nullptr;
    for (int i = 0; i < n_in; i++) {
        switch (in_sizes[i]) {
            case N_NODES * F_IN:      h   = (const float*)d_in[i]; break;
            case N_NODES * N_NODES:   adj = (const int*)d_in[i];   break;
            case F_IN * HD:           W   = (const float*)d_in[i]; break;
            case N_HEADS * 2 * N_HID: a   = (const float*)d_in[i]; break;
        }
    }
    float* out = (float*)d_out;

    uint16_t *hh, *hl, *Wh, *Wl, *adjh, *V;
    float *HT, *Y, *tgt, *tmx;
    cudaGetSymbolAddress((void**)&hh,  g_hh);
    cudaGetSymbolAddress((void**)&hl,  g_hl);
    cudaGetSymbolAddress((void**)&Wh,  g_Wh);
    cudaGetSymbolAddress((void**)&Wl,  g_Wl);
    cudaGetSymbolAddress((void**)&adjh, g_adjh);
    cudaGetSymbolAddress((void**)&V,   g_V);
    cudaGetSymbolAddress((void**)&HT,  g_HT);
    cudaGetSymbolAddress((void**)&Y,   g_Y);
    cudaGetSymbolAddress((void**)&tgt, g_tgt);
    cudaGetSymbolAddress((void**)&tmx, g_tmax);

    const int smem1 = 2 * (2 * A_TILE + 2 * B_TILE);   // 75776  (GEMM1: NA=2,NB=2,S=2 -> 2 CTA/SM)
    const int smem2 = 4 * (A_TILE + B_TILE);           // 75776  (GEMM2: S=4 -> 2 CTA/SM)
    cudaFuncSetAttribute(gemm_mma<2, 2, 2, true>,
                         cudaFuncAttributeMaxDynamicSharedMemorySize, smem1);
    cudaFuncSetAttribute(gemm_mma64<4>,
                         cudaFuncAttributeMaxDynamicSharedMemorySize, smem2);

    // 1. operand prep
    split_kernel<<<1024, 256>>>((const float4*)h, (uint4*)hh, (uint4*)hl);
    split_kernel<<<256, 256>>>((const float4*)W, (uint4*)Wh, (uint4*)Wl);
    prep_adj<<<8192, 256>>>((const int4*)adj, (uint4*)adjh);

    // 2. GEMM1: HT = h@W (dual-bf16, 3 products)  M=4096 N=1024 K=512
    gemm_mma<2, 2, 2, true><<<dim3(HD / BN, N_NODES / BM), 256, smem1>>>(
        hh, hl, Wh, Wl, HT, HD, F_IN);

    // 3. attention scalars + weighted V
    tgt_kernel <<<2048, 256>>>(HT, a, tgt);
    tmax_kernel<<<N_HEADS, 256>>>(tgt, tmx);
    buildV     <<<N_NODES, 256>>>(HT, tgt, tmx, (__half*)V);

    // 4. GEMM2: Y = adj@V (single fp16, 64x64 warp tile)  M=4096 N=1152 K=4096
    gemm_mma64<4><<<dim3(NP2 / BN, N_NODES / BM), 128, smem2>>>(
        adjh, V, Y, NP2, N_NODES);

    // 5. normalize + head mean
    final_kernel<<<N_NODES, 256>>>(Y, out);
    (void)out_size;
}

// round 5
// speedup vs baseline: 1.0181x; 1.0181x over previous
#include <cuda_runtime.h>
#include <cuda_bf16.h>
#include <cuda_fp16.h>
#include <cstdint>

// ---------------- problem constants ----------------
#define N_NODES 4096
#define F_IN    512
#define N_HEADS 4
#define N_HID   256
#define HD      1024     // N_HEADS*N_HID
#define NP2     1152     // 1024 feature cols + 4 Z cols, padded to 9*128

// ---------------- scratch (device globals; allocation-free) ----------------
__device__ uint16_t g_hh [N_NODES * F_IN];
__device__ uint16_t g_hl [N_NODES * F_IN];
__device__ uint16_t g_Wh [F_IN * HD];
__device__ uint16_t g_Wl [F_IN * HD];
__device__ uint16_t g_adjh[(size_t)N_NODES * N_NODES];
__device__ uint16_t g_V  [(size_t)N_NODES * NP2];
__device__ float    g_HT [N_NODES * HD];
__device__ float    g_Y  [(size_t)N_NODES * NP2];
__device__ float    g_tgt [N_HEADS * N_NODES];
__device__ float    g_tmax[N_HEADS];

// ---------------- small helpers ----------------
__device__ __forceinline__ uint32_t smem_u32(const void* p) {
    uint32_t a;
    asm("{ .reg .u64 t; cvta.to.shared.u64 t, %1; cvt.u32.u64 %0, t; }" : "=r"(a) : "l"(p));
    return a;
}
__device__ __forceinline__ uint32_t pk(uint16_t a, uint16_t b) {
    return (uint32_t)a | ((uint32_t)b << 16);
}
__device__ __forceinline__ void cpasync16(uint32_t dst, const void* src) {
    asm volatile("cp.async.cg.shared.global [%0], [%1], 16;" :: "r"(dst), "l"(src));
}
__device__ __forceinline__ void cp_commit() {
    asm volatile("cp.async.commit_group;" ::: "memory");
}
template <int N>
__device__ __forceinline__ void cp_wait() {
    asm volatile("cp.async.wait_group %0;" :: "n"(N) : "memory");
}
__device__ __forceinline__ void ldsm4(uint32_t& r0, uint32_t& r1, uint32_t& r2, uint32_t& r3,
                                      uint32_t addr) {
    asm volatile("ldmatrix.sync.aligned.m8n8.x4.shared.b16 {%0,%1,%2,%3}, [%4];"
                 : "=r"(r0), "=r"(r1), "=r"(r2), "=r"(r3) : "r"(addr));
}
__device__ __forceinline__ void ldsm4t(uint32_t& r0, uint32_t& r1, uint32_t& r2, uint32_t& r3,
                                       uint32_t addr) {
    asm volatile("ldmatrix.sync.aligned.m8n8.x4.trans.shared.b16 {%0,%1,%2,%3}, [%4];"
                 : "=r"(r0), "=r"(r1), "=r"(r2), "=r"(r3) : "r"(addr));
}
template <bool BF>
__device__ __forceinline__ void mma16816(float* c, const uint32_t* a, const uint32_t* b) {
    if (BF)
        asm volatile(
            "mma.sync.aligned.m16n8k16.row.col.f32.bf16.bf16.f32 "
            "{%0,%1,%2,%3},{%4,%5,%6,%7},{%8,%9},{%0,%1,%2,%3};"
            : "+f"(c[0]), "+f"(c[1]), "+f"(c[2]), "+f"(c[3])
            : "r"(a[0]), "r"(a[1]), "r"(a[2]), "r"(a[3]), "r"(b[0]), "r"(b[1]));
    else
        asm volatile(
            "mma.sync.aligned.m16n8k16.row.col.f32.f16.f16.f32 "
            "{%0,%1,%2,%3},{%4,%5,%6,%7},{%8,%9},{%0,%1,%2,%3};"
            : "+f"(c[0]), "+f"(c[1]), "+f"(c[2]), "+f"(c[3])
            : "r"(a[0]), "r"(a[1]), "r"(a[2]), "r"(a[3]), "r"(b[0]), "r"(b[1]));
}

// ---------------- prep kernels ----------------
__global__ void split_kernel(const float4* __restrict__ src,
                             uint4* __restrict__ hh, uint4* __restrict__ hl) {
    int i = blockIdx.x * 256 + threadIdx.x;
    float4 v0 = src[2 * i], v1 = src[2 * i + 1];
    float f[8] = {v0.x, v0.y, v0.z, v0.w, v1.x, v1.y, v1.z, v1.w};
    uint16_t H[8], L[8];
    #pragma unroll
    for (int j = 0; j < 8; j++) {
        __nv_bfloat16 b = __float2bfloat16(f[j]);
        H[j] = __bfloat16_as_ushort(b);
        L[j] = __bfloat16_as_ushort(__float2bfloat16(f[j] - __bfloat162float(b)));
    }
    hh[i] = make_uint4(pk(H[0], H[1]), pk(H[2], H[3]), pk(H[4], H[5]), pk(H[6], H[7]));
    hl[i] = make_uint4(pk(L[0], L[1]), pk(L[2], L[3]), pk(L[4], L[5]), pk(L[6], L[7]));
}

__global__ void prep_adj(const int4* __restrict__ adj, uint4* __restrict__ out) {
    int i = blockIdx.x * 256 + threadIdx.x;
    int4 a0 = adj[2 * i], a1 = adj[2 * i + 1];
    int v[8] = {a0.x, a0.y, a0.z, a0.w, a1.x, a1.y, a1.z, a1.w};
    uint16_t hv[8];
    #pragma unroll
    for (int j = 0; j < 8; j++) hv[j] = (v[j] > 0) ? (uint16_t)0x3C00 : (uint16_t)0;
    out[i] = make_uint4(pk(hv[0], hv[1]), pk(hv[2], hv[3]), pk(hv[4], hv[5]), pk(hv[6], hv[7]));
}

__global__ void tgt_kernel(const float* __restrict__ HT, const float* __restrict__ a,
                           float* __restrict__ tgt) {
    int warp = (blockIdx.x * blockDim.x + threadIdx.x) >> 5;
    int lane = threadIdx.x & 31;
    if (warp >= N_HEADS * N_NODES) return;
    int h = warp >> 12, m = warp & 4095;
    const float* row = HT + (size_t)m * HD + h * N_HID;
    const float* av  = a + h * (2 * N_HID) + N_HID;
    float s = 0.0f;
    #pragma unroll
    for (int d = lane; d < N_HID; d += 32) {
        float x = row[d];
        x = (x > 0.0f) ? x : 0.1f * x;
        s += x * av[d];
    }
    #pragma unroll
    for (int o = 16; o; o >>= 1) s += __shfl_xor_sync(0xFFFFFFFFu, s, o);
    if (lane == 0) tgt[h * N_NODES + m] = s;
}

__global__ void tmax_kernel(const float* __restrict__ tgt, float* __restrict__ tmax) {
    int h = blockIdx.x;
    __shared__ float sm[256];
    float m = -1e30f;
    for (int i = threadIdx.x; i < N_NODES; i += 256)
        m = fmaxf(m, tgt[h * N_NODES + i]);
    sm[threadIdx.x] = m;
    __syncthreads();
    for (int s = 128; s; s >>= 1) {
        if (threadIdx.x < s) sm[threadIdx.x] = fmaxf(sm[threadIdx.x], sm[threadIdx.x + s]);
        __syncthreads();
    }
    if (threadIdx.x == 0) tmax[h] = sm[0];
}

// w' = exp(tgt - tmax) * 4096 (scale cancels in ratio; keeps fp16 normal)
__global__ void buildV(const float* __restrict__ HT, const float* __restrict__ tgt,
                       const float* __restrict__ tmax, __half* __restrict__ V) {
    int n = blockIdx.x;
    __shared__ float w[N_HEADS];
    if (threadIdx.x < N_HEADS)
        w[threadIdx.x] = expf(tgt[threadIdx.x * N_NODES + n] - tmax[threadIdx.x]) * 4096.0f;
    __syncthreads();
    __half* row = V + (size_t)n * NP2;
    const float* ht = HT + (size_t)n * HD;
    for (int c = threadIdx.x; c < NP2; c += 256) {
        float v;
        if (c < HD)          v = w[c >> 8] * ht[c];
        else if (c < HD + 4) v = w[c - HD];
        else                 v = 0.0f;
        row[c] = __float2half(v);
    }
}

__global__ void final_kernel(const float* __restrict__ Y, float* __restrict__ out) {
    int i = blockIdx.x * 256 + threadIdx.x;
    int n = i >> 8, d = i & 255;
    const float* yr = Y + (size_t)n * NP2;
    float acc = 0.0f;
    #pragma unroll
    for (int h = 0; h < N_HEADS; h++)
        acc += yr[h * N_HID + d] / yr[HD + h];
    out[i] = 0.25f * acc;
}

// ---------------- shared GEMM geometry ----------------
#define BK 32
#define A_STRIDE 80      // bytes: 64B data + 16B pad per row
#define B_STRIDE 272     // bytes: 256B data + 16B pad per row
#define A_TILE1  (128 * A_STRIDE)  // 10240 B (GEMM1, BM=128)
#define B_TILE1  (BK * B_STRIDE)   // 8704 B
#define A_TILE2  (256 * A_STRIDE)  // 20480 B (GEMM2, BM=256)
#define STAGE2   (A_TILE2 + B_TILE1)  // 29184 B

// ---------------- GEMM1: BM=128 BN=128, 8 warps (2x4), warp 64x32, multi-product ------
template <int NA, int NB, int STAGES, bool BF>
__global__ void __launch_bounds__(256)
gemm_mma(const uint16_t* __restrict__ A1, const uint16_t* __restrict__ A2,
         const uint16_t* __restrict__ B1, const uint16_t* __restrict__ B2,
         float* __restrict__ C, int N, int K) {
    extern __shared__ __align__(128) char smem[];
    const uint32_t sb = smem_u32(smem);
    const int tid = threadIdx.x, lane = tid & 31, wid = tid >> 5;
    const int wm = wid >> 2, wn = wid & 3;
    const int bm = blockIdx.y * 128, bn = blockIdx.x * 128;
    constexpr uint32_t STAGE = NA * A_TILE1 + NB * B_TILE1;

    const uint16_t* Ap[2] = {A1, A2};
    const uint16_t* Bp[2] = {B1, B2};

    const int arow = tid >> 2, ac16 = tid & 3;
    const int brow = tid >> 4, bc16 = tid & 15;

    auto load_stage = [&](int slot, int k0) {
        uint32_t base = sb + slot * STAGE;
        #pragma unroll
        for (int p = 0; p < NA; p++) {
            uint32_t ab = base + p * A_TILE1;
            const uint16_t* g = Ap[p] + (size_t)(bm + arow) * K + k0 + ac16 * 8;
            cpasync16(ab + arow * A_STRIDE + ac16 * 16, g);
            cpasync16(ab + (arow + 64) * A_STRIDE + ac16 * 16, g + (size_t)64 * K);
        }
        #pragma unroll
        for (int p = 0; p < NB; p++) {
            uint32_t bb = base + NA * A_TILE1 + p * B_TILE1;
            const uint16_t* g = Bp[p] + (size_t)(k0 + brow) * N + bn + bc16 * 8;
            cpasync16(bb + brow * B_STRIDE + bc16 * 16, g);
            cpasync16(bb + (brow + 16) * B_STRIDE + bc16 * 16, g + (size_t)16 * N);
        }
        cp_commit();
    };

    const int iters = K / BK;
    #pragma unroll
    for (int s = 0; s < STAGES - 1; s++)
        load_stage(s, s * BK);

    float acc[4][4][4];
    #pragma unroll
    for (int i = 0; i < 4; i++)
        #pragma unroll
        for (int j = 0; j < 4; j++)
            #pragma unroll
            for (int r = 0; r < 4; r++) acc[i][j][r] = 0.0f;

    const int lrow = lane & 15;
    const int lcol = lane >> 4;

    for (int it = 0; it < iters; ++it) {
        cp_wait<STAGES - 2>();
        __syncthreads();
        if (it + STAGES - 1 < iters)
            load_stage((it + STAGES - 1) % STAGES, (it + STAGES - 1) * BK);

        uint32_t base = sb + (it % STAGES) * STAGE;
        #pragma unroll
        for (int ks = 0; ks < 2; ks++) {
            uint32_t af[2][4][4];
            uint32_t bf[2][2][4];
            #pragma unroll
            for (int p = 0; p < NA; p++)
                #pragma unroll
                for (int mt = 0; mt < 4; mt++) {
                    uint32_t addr = base + p * A_TILE1
                                  + (wm * 64 + mt * 16 + lrow) * A_STRIDE
                                  + ks * 32 + lcol * 16;
                    ldsm4(af[p][mt][0], af[p][mt][1], af[p][mt][2], af[p][mt][3], addr);
                }
            #pragma unroll
            for (int p = 0; p < NB; p++)
                #pragma unroll
                for (int nt2 = 0; nt2 < 2; nt2++) {
                    uint32_t addr = base + NA * A_TILE1 + p * B_TILE1
                                  + (ks * 16 + lrow) * B_STRIDE
                                  + (wn * 32 + nt2 * 16 + lcol * 8) * 2;
                    ldsm4t(bf[p][nt2][0], bf[p][nt2][1], bf[p][nt2][2], bf[p][nt2][3], addr);
                }
            #pragma unroll
            for (int mt = 0; mt < 4; mt++)
                #pragma unroll
                for (int nt = 0; nt < 4; nt++) {
                    const uint32_t* b0 = &bf[0][nt >> 1][(nt & 1) * 2];
                    mma16816<BF>(acc[mt][nt], af[0][mt], b0);
                    if (NB == 2) mma16816<BF>(acc[mt][nt], af[0][mt], &bf[1][nt >> 1][(nt & 1) * 2]);
                    if (NA == 2) mma16816<BF>(acc[mt][nt], af[1][mt], b0);
                }
        }
    }

    const int row0 = bm + wm * 64;
    const int col0 = bn + wn * 32;
    #pragma unroll
    for (int mt = 0; mt < 4; mt++)
        #pragma unroll
        for (int nt = 0; nt < 4; nt++) {
            int r = row0 + mt * 16 + (lane >> 2);
            int c = col0 + nt * 8 + (lane & 3) * 2;
            *(float2*)&C[(size_t)r * N + c]       = make_float2(acc[mt][nt][0], acc[mt][nt][1]);
            *(float2*)&C[(size_t)(r + 8) * N + c] = make_float2(acc[mt][nt][2], acc[mt][nt][3]);
        }
}

// ---------------- GEMM2: BM=256 BN=128, 8 warps (4x2), warp 64x64, fp16 --------------
template <int STAGES>
__global__ void __launch_bounds__(256)
gemm2(const uint16_t* __restrict__ A, const uint16_t* __restrict__ B,
      float* __restrict__ C, int N, int K) {
    extern __shared__ __align__(128) char smem[];
    const uint32_t sb = smem_u32(smem);
    const int tid = threadIdx.x, lane = tid & 31, wid = tid >> 5;
    const int wm = wid >> 1, wn = wid & 1;
    const int bm = blockIdx.y * 256, bn = blockIdx.x * 128;

    auto load_stage = [&](int slot, int k0) {
        uint32_t base = sb + slot * STAGE2;
        #pragma unroll
        for (int i = 0; i < 4; i++) {                // A: 1024 chunks of 16B
            int idx = i * 256 + tid;
            int row = idx >> 2, c16 = idx & 3;
            cpasync16(base + row * A_STRIDE + c16 * 16,
                      A + (size_t)(bm + row) * K + k0 + c16 * 8);
        }
        #pragma unroll
        for (int i = 0; i < 2; i++) {                // B: 512 chunks of 16B
            int idx = i * 256 + tid;
            int row = idx >> 4, c16 = idx & 15;
            cpasync16(base + A_TILE2 + row * B_STRIDE + c16 * 16,
                      B + (size_t)(k0 + row) * N + bn + c16 * 8);
        }
        cp_commit();
    };

    const int iters = K / BK;
    #pragma unroll
    for (int s = 0; s < STAGES - 1; s++)
        load_stage(s, s * BK);

    float acc[4][8][4];
    #pragma unroll
    for (int i = 0; i < 4; i++)
        #pragma unroll
        for (int j = 0; j < 8; j++)
            #pragma unroll
            for (int r = 0; r < 4; r++) acc[i][j][r] = 0.0f;

    const int lrow = lane & 15;
    const int lcol = lane >> 4;

    for (int it = 0; it < iters; ++it) {
        cp_wait<STAGES - 2>();
        __syncthreads();
        if (it + STAGES - 1 < iters)
            load_stage((it + STAGES - 1) % STAGES, (it + STAGES - 1) * BK);

        uint32_t base = sb + (it % STAGES) * STAGE2;
        #pragma unroll
        for (int ks = 0; ks < 2; ks++) {
            uint32_t af[4][4];
            uint32_t bf[4][4];
            #pragma unroll
            for (int mt = 0; mt < 4; mt++) {
                uint32_t addr = base + (wm * 64 + mt * 16 + lrow) * A_STRIDE
                              + ks * 32 + lcol * 16;
                ldsm4(af[mt][0], af[mt][1], af[mt][2], af[mt][3], addr);
            }
            #pragma unroll
            for (int nt2 = 0; nt2 < 4; nt2++) {
                uint32_t addr = base + A_TILE2 + (ks * 16 + lrow) * B_STRIDE
                              + (wn * 64 + nt2 * 16 + lcol * 8) * 2;
                ldsm4t(bf[nt2][0], bf[nt2][1], bf[nt2][2], bf[nt2][3], addr);
            }
            #pragma unroll
            for (int mt = 0; mt < 4; mt++)
                #pragma unroll
                for (int nt = 0; nt < 8; nt++)
                    mma16816<false>(acc[mt][nt], af[mt], &bf[nt >> 1][(nt & 1) * 2]);
        }
    }

    const int row0 = bm + wm * 64;
    const int col0 = bn + wn * 64;
    #pragma unroll
    for (int mt = 0; mt < 4; mt++)
        #pragma unroll
        for (int nt = 0; nt < 8; nt++) {
            int r = row0 + mt * 16 + (lane >> 2);
            int c = col0 + nt * 8 + (lane & 3) * 2;
            *(float2*)&C[(size_t)r * N + c]       = make_float2(acc[mt][nt][0], acc[mt][nt][1]);
            *(float2*)&C[(size_t)(r + 8) * N + c] = make_float2(acc[mt][nt][2], acc[mt][nt][3]);
        }
}

// ---------------- launch ----------------
extern "C" void kernel_launch(void* const* d_in, const int* in_sizes, int n_in,
                              void* d_out, int out_size) {
    const float* h = nullptr; const int* adj = nullptr;
    const float* W = nullptr; const float* a = nullptr;
    for (int i = 0; i < n_in; i++) {
        switch (in_sizes[i]) {
            case N_NODES * F_IN:      h   = (const float*)d_in[i]; break;
            case N_NODES * N_NODES:   adj = (const int*)d_in[i];   break;
            case F_IN * HD:           W   = (const float*)d_in[i]; break;
            case N_HEADS * 2 * N_HID: a   = (const float*)d_in[i]; break;
        }
    }
    float* out = (float*)d_out;

    uint16_t *hh, *hl, *Wh, *Wl, *adjh, *V;
    float *HT, *Y, *tgt, *tmx;
    cudaGetSymbolAddress((void**)&hh,  g_hh);
    cudaGetSymbolAddress((void**)&hl,  g_hl);
    cudaGetSymbolAddress((void**)&Wh,  g_Wh);
    cudaGetSymbolAddress((void**)&Wl,  g_Wl);
    cudaGetSymbolAddress((void**)&adjh, g_adjh);
    cudaGetSymbolAddress((void**)&V,   g_V);
    cudaGetSymbolAddress((void**)&HT,  g_HT);
    cudaGetSymbolAddress((void**)&Y,   g_Y);
    cudaGetSymbolAddress((void**)&tgt, g_tgt);
    cudaGetSymbolAddress((void**)&tmx, g_tmax);

    const int smem1 = 3 * (2 * A_TILE1 + 2 * B_TILE1);   // 113664 (GEMM1: S=3, proven)
    const int smem2 = 3 * STAGE2;                        //  87552 (GEMM2: S=3)
    cudaFuncSetAttribute(gemm_mma<2, 2, 3, true>,
                         cudaFuncAttributeMaxDynamicSharedMemorySize, smem1);
    cudaFuncSetAttribute(gemm2<3>,
                         cudaFuncAttributeMaxDynamicSharedMemorySize, smem2);

    // 1. operand prep
    split_kernel<<<1024, 256>>>((const float4*)h, (uint4*)hh, (uint4*)hl);
    split_kernel<<<256, 256>>>((const float4*)W, (uint4*)Wh, (uint4*)Wl);
    prep_adj<<<8192, 256>>>((const int4*)adj, (uint4*)adjh);

    // 2. GEMM1: HT = h@W (dual-bf16, 3 products)  M=4096 N=1024 K=512
    gemm_mma<2, 2, 3, true><<<dim3(HD / 128, N_NODES / 128), 256, smem1>>>(
        hh, hl, Wh, Wl, HT, HD, F_IN);

    // 3. attention scalars + weighted V
    tgt_kernel <<<2048, 256>>>(HT, a, tgt);
    tmax_kernel<<<N_HEADS, 256>>>(tgt, tmx);
    buildV     <<<N_NODES, 256>>>(HT, tgt, tmx, (__half*)V);

    // 4. GEMM2: Y = adj@V (fp16, BM=256, warp 64x64)  M=4096 N=1152 K=4096, 144 CTAs
    gemm2<3><<<dim3(NP2 / 128, N_NODES / 256), 256, smem2>>>(
        adjh, V, Y, NP2, N_NODES);

    // 5. normalize + head mean
    final_kernel<<<N_NODES, 256>>>(Y, out);
    (void)out_size;
}